// round 13
// baseline (speedup 1.0000x reference)
#include <cuda_runtime.h>
#include <cuda_bf16.h>
#include <cstdint>
#include <stdint.h>
#include <math.h>

// Problem constants (fixed by the registry shapes)
#define NN 50000
#define NE 1000000
#define FF 256
#define NC 300
#define ED 64

// ---------------- device scratch (no runtime allocation allowed) -------------
__device__ float g_H[(size_t)NN * 512];     // [:,0:256]=h, [:,256:512]=h_agg
__device__ float g_T[(size_t)NN * NC];      // content proj temp
__device__ float g_T2[(size_t)NN * FF];     // conv output
__device__ float g_T3[(size_t)NN * FF];     // Wo1 output
__device__ int   g_deg[NN];
__device__ int   g_off[NN + 1];
__device__ int   g_cursor[NN];
__device__ int   g_csr[NE];
__device__ int   g_bsum[64];

// ---------------- small helpers ----------------------------------------------
__device__ __forceinline__ float lrelu(float x) { return x > 0.f ? x : 0.1f * x; }
__device__ __forceinline__ float4 f4add(float4 a, float4 b) {
    return make_float4(a.x + b.x, a.y + b.y, a.z + b.z, a.w + b.w);
}

// D(16x8) += A(16x16,row) * B(16x8,col) in bf16, fp32 accum
__device__ __forceinline__ void mma16(float* c, const unsigned int* a, const unsigned int* b) {
    asm volatile(
        "mma.sync.aligned.m16n8k16.row.col.f32.bf16.bf16.f32 "
        "{%0,%1,%2,%3},{%4,%5,%6,%7},{%8,%9},{%0,%1,%2,%3};"
        : "+f"(c[0]), "+f"(c[1]), "+f"(c[2]), "+f"(c[3])
        : "r"(a[0]), "r"(a[1]), "r"(a[2]), "r"(a[3]), "r"(b[0]), "r"(b[1]));
}

// split two floats into packed bf16x2 hi / lo parts
__device__ __forceinline__ void split2(float x0, float x1,
                                       unsigned int& hi, unsigned int& lo) {
    __nv_bfloat16 h0 = __float2bfloat16(x0);
    __nv_bfloat16 h1 = __float2bfloat16(x1);
    float r0 = x0 - __bfloat162float(h0);
    float r1 = x1 - __bfloat162float(h1);
    __nv_bfloat16 l0 = __float2bfloat16(r0);
    __nv_bfloat16 l1 = __float2bfloat16(r1);
    __nv_bfloat162 H = __halves2bfloat162(h0, h1);
    __nv_bfloat162 L = __halves2bfloat162(l0, l1);
    hi = *(unsigned int*)&H;
    lo = *(unsigned int*)&L;
}

// ---------------- CSR build ---------------------------------------------------
__global__ void k_zero_int(int* p, int n) {
    for (int i = blockIdx.x * blockDim.x + threadIdx.x; i < n; i += gridDim.x * blockDim.x)
        p[i] = 0;
}

__global__ void k_hist(const int* __restrict__ dst, int e) {
    for (int i = blockIdx.x * blockDim.x + threadIdx.x; i < e; i += gridDim.x * blockDim.x)
        atomicAdd(&g_deg[dst[i]], 1);
}

__global__ void k_scan1(int n) {
    __shared__ int s[1024];
    int t = threadIdx.x;
    int i = blockIdx.x * 1024 + t;
    int x = (i < n) ? g_deg[i] : 0;
    s[t] = x;
    __syncthreads();
    #pragma unroll
    for (int d = 1; d < 1024; d <<= 1) {
        int v = (t >= d) ? s[t - d] : 0;
        __syncthreads();
        s[t] += v;
        __syncthreads();
    }
    if (i < n) g_off[i + 1] = s[t];
    if (t == 1023) g_bsum[blockIdx.x] = s[t];
}

__global__ void k_scan2(int nb) {
    if (threadIdx.x == 0 && blockIdx.x == 0) {
        int run = 0;
        for (int b = 0; b < nb; b++) { int v = g_bsum[b]; g_bsum[b] = run; run += v; }
        g_off[0] = 0;
    }
}

__global__ void k_scan3(int n) {
    for (int i = blockIdx.x * blockDim.x + threadIdx.x; i < n; i += gridDim.x * blockDim.x) {
        int o = g_off[i + 1] + g_bsum[i >> 10];
        g_off[i + 1] = o;
    }
}

__global__ void k_cursor(int n) {
    for (int i = blockIdx.x * blockDim.x + threadIdx.x; i < n; i += gridDim.x * blockDim.x)
        g_cursor[i] = g_off[i];
}

__global__ void k_fill(const int* __restrict__ src, const int* __restrict__ dst, int e) {
    for (int i = blockIdx.x * blockDim.x + threadIdx.x; i < e; i += gridDim.x * blockDim.x) {
        int v = dst[i];
        int p = atomicAdd(&g_cursor[v], 1);
        g_csr[p] = src[i];
    }
}

// ---------------- neighbor aggregation (warp per node, CSR gather) -----------
__global__ void k_agg(int n) {
    int warp = (blockIdx.x * blockDim.x + threadIdx.x) >> 5;
    int lane = threadIdx.x & 31;
    if (warp >= n) return;
    int beg = g_off[warp], end = g_off[warp + 1];
    float4 a0 = make_float4(0, 0, 0, 0), a1 = make_float4(0, 0, 0, 0);
    int e = beg;
    for (; e + 1 < end; e += 2) {
        int s0 = g_csr[e], s1 = g_csr[e + 1];
        const float4* p0 = (const float4*)(g_H + (size_t)s0 * 512) + lane * 2;
        const float4* p1 = (const float4*)(g_H + (size_t)s1 * 512) + lane * 2;
        float4 x0 = p0[0], x1 = p0[1];
        float4 y0 = p1[0], y1 = p1[1];
        a0 = f4add(a0, x0); a1 = f4add(a1, x1);
        a0 = f4add(a0, y0); a1 = f4add(a1, y1);
    }
    if (e < end) {
        int s0 = g_csr[e];
        const float4* p0 = (const float4*)(g_H + (size_t)s0 * 512) + lane * 2;
        a0 = f4add(a0, p0[0]); a1 = f4add(a1, p0[1]);
    }
    int deg = end - beg;
    float inv = 1.f / (float)(deg > 0 ? deg : 1);
    a0.x *= inv; a0.y *= inv; a0.z *= inv; a0.w *= inv;
    a1.x *= inv; a1.y *= inv; a1.z *= inv; a1.w *= inv;
    float4* o = (float4*)(g_H + (size_t)warp * 512 + 256) + lane * 2;
    o[0] = a0; o[1] = a1;
}

// ---------------- row L2-normalize (warp per row, width 256) -----------------
__global__ void k_norm(const float* __restrict__ src, float* __restrict__ dst, int n) {
    int warp = (blockIdx.x * blockDim.x + threadIdx.x) >> 5;
    int lane = threadIdx.x & 31;
    if (warp >= n) return;
    const float4* p = (const float4*)(src + (size_t)warp * 256) + lane * 2;
    float4 a = p[0], b = p[1];
    float s = a.x * a.x + a.y * a.y + a.z * a.z + a.w * a.w
            + b.x * b.x + b.y * b.y + b.z * b.z + b.w * b.w;
    #pragma unroll
    for (int m = 16; m > 0; m >>= 1) s += __shfl_xor_sync(0xffffffffu, s, m);
    float scale = 1.f / fmaxf(sqrtf(s), 1e-6f);
    a.x *= scale; a.y *= scale; a.z *= scale; a.w *= scale;
    b.x *= scale; b.y *= scale; b.z *= scale; b.w *= scale;
    float4* o = (float4*)(dst + (size_t)warp * 256) + lane * 2;
    o[0] = a; o[1] = b;
}

// ---------------- 3-term BF16-split tensor-core GEMM --------------------------
// C = [res +] act(A @ W^T + bias)
// A: M x K (lda), W: N x K row-major (ldw), C: M x N (ldc)
// Block tile 128x128, 8 warps (2m x 4n) of 64x32, K-chunk 32 (bf16, m16n8k16).
// SMEM [row][kpair] uint32 layout, stride 20 -> conflict-free fragment LDS.

#define SST 20   // smem row stride in uint32 (16 + 4 pad)

__device__ __forceinline__ float4 ldguard(const float* row, int k, int K) {
    float4 v = make_float4(0.f, 0.f, 0.f, 0.f);
    if (row) {
        if (k + 4 <= K) {
            v = *(const float4*)(row + k);
        } else {
            if (k + 0 < K) v.x = row[k + 0];
            if (k + 1 < K) v.y = row[k + 1];
            if (k + 2 < K) v.z = row[k + 2];
            if (k + 3 < K) v.w = row[k + 3];
        }
    }
    return v;
}

template <int ACT, bool RES, bool GATHER>
__global__ __launch_bounds__(256, 1)
void k_gemm_tc(const float* __restrict__ A, int lda,
               const float* __restrict__ W, int ldw,
               const float* __restrict__ bias,
               float* __restrict__ C, int ldc,
               const int* __restrict__ rowidx,
               int M, int N, int K) {
    __shared__ unsigned int Ah[128 * SST], Al[128 * SST];
    __shared__ unsigned int Bh[128 * SST], Bl[128 * SST];

    const int t = threadIdx.x;
    const int wid = t >> 5, lane = t & 31;
    const int wm = (wid & 1) * 64;        // warp m offset in block
    const int wn = (wid >> 1) * 32;       // warp n offset in block
    const int bm = blockIdx.y * 128;
    const int bn = blockIdx.x * 128;

    // loader coords: each thread handles one row, 16 consecutive K floats
    const int lr = t >> 1;                 // 0..127 row in tile
    const int lk = (t & 1) * 16;           // 0 or 16 float offset in chunk

    const float* Arow = nullptr;
    if (bm + lr < M) {
        int r = GATHER ? rowidx[bm + lr] : (bm + lr);
        Arow = A + (size_t)r * lda;
    }
    const float* Brow = (bn + lr < N) ? (W + (size_t)(bn + lr) * ldw) : nullptr;

    float acc[4][4][4];
    #pragma unroll
    for (int i = 0; i < 4; i++)
        #pragma unroll
        for (int j = 0; j < 4; j++)
            #pragma unroll
            for (int r = 0; r < 4; r++) acc[i][j][r] = 0.f;

    const int nch = (K + 31) >> 5;

    // prefetch chunk 0 (4 float4 of A, 4 of B per thread)
    float4 va[4], vb[4];
    #pragma unroll
    for (int q = 0; q < 4; q++) {
        va[q] = ldguard(Arow, lk + q * 4, K);
        vb[q] = ldguard(Brow, lk + q * 4, K);
    }

    for (int c = 0; c < nch; c++) {
        // split + pack + store: 8 uint32 per array per thread (2 x uint4 STS)
        {
            unsigned int ph[8], pl[8];
            #pragma unroll
            for (int q = 0; q < 4; q++) {
                split2(va[q].x, va[q].y, ph[q * 2 + 0], pl[q * 2 + 0]);
                split2(va[q].z, va[q].w, ph[q * 2 + 1], pl[q * 2 + 1]);
            }
            int base = lr * SST + lk / 2;
            *(uint4*)(Ah + base)     = make_uint4(ph[0], ph[1], ph[2], ph[3]);
            *(uint4*)(Ah + base + 4) = make_uint4(ph[4], ph[5], ph[6], ph[7]);
            *(uint4*)(Al + base)     = make_uint4(pl[0], pl[1], pl[2], pl[3]);
            *(uint4*)(Al + base + 4) = make_uint4(pl[4], pl[5], pl[6], pl[7]);
            #pragma unroll
            for (int q = 0; q < 4; q++) {
                split2(vb[q].x, vb[q].y, ph[q * 2 + 0], pl[q * 2 + 0]);
                split2(vb[q].z, vb[q].w, ph[q * 2 + 1], pl[q * 2 + 1]);
            }
            *(uint4*)(Bh + base)     = make_uint4(ph[0], ph[1], ph[2], ph[3]);
            *(uint4*)(Bh + base + 4) = make_uint4(ph[4], ph[5], ph[6], ph[7]);
            *(uint4*)(Bl + base)     = make_uint4(pl[0], pl[1], pl[2], pl[3]);
            *(uint4*)(Bl + base + 4) = make_uint4(pl[4], pl[5], pl[6], pl[7]);
        }
        __syncthreads();

        if (c + 1 < nch) {
            int kn = (c + 1) * 32 + lk;
            #pragma unroll
            for (int q = 0; q < 4; q++) {
                va[q] = ldguard(Arow, kn + q * 4, K);
                vb[q] = ldguard(Brow, kn + q * 4, K);
            }
        }

        #pragma unroll
        for (int ks = 0; ks < 2; ks++) {        // two k16 sub-steps per chunk
            const int kc = ks * 8 + (lane & 3); // uint32 col index
            unsigned int ah[4][4], al[4][4];
            #pragma unroll
            for (int i = 0; i < 4; i++) {
                int m = wm + i * 16 + (lane >> 2);
                ah[i][0] = Ah[m * SST + kc];
                ah[i][1] = Ah[(m + 8) * SST + kc];
                ah[i][2] = Ah[m * SST + kc + 4];
                ah[i][3] = Ah[(m + 8) * SST + kc + 4];
                al[i][0] = Al[m * SST + kc];
                al[i][1] = Al[(m + 8) * SST + kc];
                al[i][2] = Al[m * SST + kc + 4];
                al[i][3] = Al[(m + 8) * SST + kc + 4];
            }
            unsigned int bh[4][2], bl[4][2];
            #pragma unroll
            for (int j = 0; j < 4; j++) {
                int n = wn + j * 8 + (lane >> 2);
                bh[j][0] = Bh[n * SST + kc];
                bh[j][1] = Bh[n * SST + kc + 4];
                bl[j][0] = Bl[n * SST + kc];
                bl[j][1] = Bl[n * SST + kc + 4];
            }
            #pragma unroll
            for (int i = 0; i < 4; i++)
                #pragma unroll
                for (int j = 0; j < 4; j++) {
                    mma16(acc[i][j], ah[i], bh[j]);   // hi*hi
                    mma16(acc[i][j], al[i], bh[j]);   // lo*hi
                    mma16(acc[i][j], ah[i], bl[j]);   // hi*lo
                }
        }
        __syncthreads();
    }

    // epilogue: c0=(g,2t) c1=(g,2t+1) c2=(g+8,2t) c3=(g+8,2t+1)
    #pragma unroll
    for (int i = 0; i < 4; i++) {
        #pragma unroll
        for (int half = 0; half < 2; half++) {
            int gm = bm + wm + i * 16 + (lane >> 2) + half * 8;
            if (gm >= M) continue;
            #pragma unroll
            for (int j = 0; j < 4; j++) {
                int gn = bn + wn + j * 8 + (lane & 3) * 2;
                if (gn >= N) continue;  // N is even, so gn+1 < N too
                float v0 = acc[i][j][half * 2 + 0] + bias[gn];
                float v1 = acc[i][j][half * 2 + 1] + bias[gn + 1];
                if (ACT == 1) { v0 = lrelu(v0); v1 = lrelu(v1); }
                size_t idx = (size_t)gm * ldc + gn;
                if (RES) { v0 += C[idx]; v1 += C[idx + 1]; }
                *(float2*)(C + idx) = make_float2(v0, v1);
            }
        }
    }
}

// ---------------- launch ------------------------------------------------------
static inline int cdiv(int a, int b) { return (a + b - 1) / b; }

extern "C" void kernel_launch(void* const* d_in, const int* in_sizes, int n_in,
                              void* d_out, int out_size) {
    const int*   node_ids = (const int*)  d_in[0];
    const float* content  = (const float*)d_in[1];
    const int*   src      = (const int*)  d_in[2];
    const int*   dst      = (const int*)  d_in[3];
    const float* emb      = (const float*)d_in[4];
    const float* W_exp    = (const float*)d_in[5];
    const float* b_exp    = (const float*)d_in[6];
    const float* W_p1     = (const float*)d_in[7];
    const float* b_p1     = (const float*)d_in[8];
    const float* W_p2     = (const float*)d_in[9];
    const float* b_p2     = (const float*)d_in[10];
    const float* W_conv   = (const float*)d_in[11];
    const float* b_conv   = (const float*)d_in[12];
    const float* Wo1      = (const float*)d_in[13];
    const float* bo1      = (const float*)d_in[14];
    const float* Wo2      = (const float*)d_in[15];
    const float* bo2      = (const float*)d_in[16];
    float* out = (float*)d_out;

    const int N = in_sizes[0];   // 50000
    const int E = in_sizes[2];   // 1000000

    float* H  = nullptr; cudaGetSymbolAddress((void**)&H,  g_H);
    float* T  = nullptr; cudaGetSymbolAddress((void**)&T,  g_T);
    float* T2 = nullptr; cudaGetSymbolAddress((void**)&T2, g_T2);
    float* T3 = nullptr; cudaGetSymbolAddress((void**)&T3, g_T3);
    int* degp = nullptr; cudaGetSymbolAddress((void**)&degp, g_deg);

    // ---- CSR build ----
    k_zero_int<<<cdiv(N, 256), 256>>>(degp, N);
    k_hist<<<cdiv(E, 256), 256>>>(dst, E);
    int nb = cdiv(N, 1024);
    k_scan1<<<nb, 1024>>>(N);
    k_scan2<<<1, 32>>>(nb);
    k_scan3<<<cdiv(N, 256), 256>>>(N);
    k_cursor<<<cdiv(N, 256), 256>>>(N);
    k_fill<<<cdiv(E, 256), 256>>>(src, dst, E);

    const int MB = cdiv(N, 128);

    // ---- initial representation ----
    {   // h = lrelu(emb[node_ids] @ W_exp^T + b_exp)  -> H[:, :256]
        dim3 g(cdiv(FF, 128), MB);
        k_gemm_tc<1, false, true><<<g, 256>>>(emb, ED, W_exp, ED, b_exp, H, 512,
                                              node_ids, N, FF, ED);
    }
    {   // T = lrelu(content @ W_p1^T + b_p1)
        dim3 g(cdiv(NC, 128), MB);
        k_gemm_tc<1, false, false><<<g, 256>>>(content, NC, W_p1, NC, b_p1, T, NC,
                                               nullptr, N, NC, NC);
    }
    {   // H[:, :256] += lrelu(T @ W_p2^T + b_p2)
        dim3 g(cdiv(FF, 128), MB);
        k_gemm_tc<1, true, false><<<g, 256>>>(T, NC, W_p2, NC, b_p2, H, 512,
                                              nullptr, N, FF, NC);
    }

    // ---- layers ----
    for (int i = 0; i < 3; i++) {
        // h_agg = segment_mean(h[src] over dst)  -> H[:, 256:512]
        k_agg<<<cdiv(N * 32, 256), 256>>>(N);

        // conv: T2 = act([h, h_agg] @ W_conv[i]^T + b_conv[i])
        dim3 g(cdiv(FF, 128), MB);
        const float* Wc = W_conv + (size_t)i * FF * 2 * FF;
        const float* bc = b_conv + (size_t)i * FF;
        if (i < 2)
            k_gemm_tc<1, false, false><<<g, 256>>>(H, 512, Wc, 2 * FF, bc, T2, FF,
                                                   nullptr, N, FF, 2 * FF);
        else
            k_gemm_tc<0, false, false><<<g, 256>>>(H, 512, Wc, 2 * FF, bc, T2, FF,
                                                   nullptr, N, FF, 2 * FF);

        // row L2 normalize
        float* ndst = (i == 2) ? out : T2;
        k_norm<<<cdiv(N * 32, 256), 256>>>(T2, ndst, N);

        if (i < 2) {
            const float* w1 = Wo1 + (size_t)i * FF * FF;
            const float* w2 = Wo2 + (size_t)i * FF * FF;
            const float* c1 = bo1 + (size_t)i * FF;
            const float* c2 = bo2 + (size_t)i * FF;
            // T3 = lrelu(T2 @ Wo1^T + bo1)
            k_gemm_tc<1, false, false><<<g, 256>>>(T2, FF, w1, FF, c1, T3, FF,
                                                   nullptr, N, FF, FF);
            // H[:, :256] = T3 @ Wo2^T + bo2
            k_gemm_tc<0, false, false><<<g, 256>>>(T3, FF, w2, FF, c2, H, 512,
                                                   nullptr, N, FF, FF);
        }
    }
}

// round 14
// speedup vs baseline: 1.1551x; 1.1551x over previous
#include <cuda_runtime.h>
#include <cuda_fp16.h>
#include <cuda_bf16.h>
#include <cstdint>
#include <stdint.h>
#include <math.h>

// Problem constants (fixed by the registry shapes)
#define NN 50000
#define NE 1000000
#define FF 256
#define NC 300
#define ED 64

// ---------------- device scratch (no runtime allocation allowed) -------------
__device__ float g_H[(size_t)NN * 512];     // [:,0:256]=h, [:,256:512]=h_agg
__device__ float g_T[(size_t)NN * NC];      // content proj temp
__device__ float g_T2[(size_t)NN * FF];     // conv output
__device__ float g_T3[(size_t)NN * FF];     // Wo1 output
__device__ int   g_deg[NN];
__device__ int   g_off[NN + 1];
__device__ int   g_cursor[NN];
__device__ int   g_csr[NE];
__device__ int   g_bsum[64];

// ---------------- small helpers ----------------------------------------------
__device__ __forceinline__ float lrelu(float x) { return x > 0.f ? x : 0.1f * x; }
__device__ __forceinline__ float4 f4add(float4 a, float4 b) {
    return make_float4(a.x + b.x, a.y + b.y, a.z + b.z, a.w + b.w);
}

// D(16x8) += A(16x16,row) * B(16x8,col) in fp16, fp32 accum
__device__ __forceinline__ void mma16(float* c, const unsigned int* a, const unsigned int* b) {
    asm volatile(
        "mma.sync.aligned.m16n8k16.row.col.f32.f16.f16.f32 "
        "{%0,%1,%2,%3},{%4,%5,%6,%7},{%8,%9},{%0,%1,%2,%3};"
        : "+f"(c[0]), "+f"(c[1]), "+f"(c[2]), "+f"(c[3])
        : "r"(a[0]), "r"(a[1]), "r"(a[2]), "r"(a[3]), "r"(b[0]), "r"(b[1]));
}

// split two floats into packed fp16x2 hi / lo parts
__device__ __forceinline__ void split2(float x0, float x1,
                                       unsigned int& hi, unsigned int& lo) {
    __half h0 = __float2half(x0);
    __half h1 = __float2half(x1);
    float r0 = x0 - __half2float(h0);
    float r1 = x1 - __half2float(h1);
    __half l0 = __float2half(r0);
    __half l1 = __float2half(r1);
    __half2 H = __halves2half2(h0, h1);
    __half2 L = __halves2half2(l0, l1);
    hi = *(unsigned int*)&H;
    lo = *(unsigned int*)&L;
}

// round two floats into packed fp16x2
__device__ __forceinline__ unsigned int pack2(float x0, float x1) {
    __half2 H = __halves2half2(__float2half(x0), __float2half(x1));
    return *(unsigned int*)&H;
}

// ---------------- CSR build ---------------------------------------------------
__global__ void k_zero_int(int* p, int n) {
    for (int i = blockIdx.x * blockDim.x + threadIdx.x; i < n; i += gridDim.x * blockDim.x)
        p[i] = 0;
}

__global__ void k_hist(const int* __restrict__ dst, int e) {
    for (int i = blockIdx.x * blockDim.x + threadIdx.x; i < e; i += gridDim.x * blockDim.x)
        atomicAdd(&g_deg[dst[i]], 1);
}

__global__ void k_scan1(int n) {
    __shared__ int s[1024];
    int t = threadIdx.x;
    int i = blockIdx.x * 1024 + t;
    int x = (i < n) ? g_deg[i] : 0;
    s[t] = x;
    __syncthreads();
    #pragma unroll
    for (int d = 1; d < 1024; d <<= 1) {
        int v = (t >= d) ? s[t - d] : 0;
        __syncthreads();
        s[t] += v;
        __syncthreads();
    }
    if (i < n) g_off[i + 1] = s[t];
    if (t == 1023) g_bsum[blockIdx.x] = s[t];
}

__global__ void k_scan2(int nb) {
    if (threadIdx.x == 0 && blockIdx.x == 0) {
        int run = 0;
        for (int b = 0; b < nb; b++) { int v = g_bsum[b]; g_bsum[b] = run; run += v; }
        g_off[0] = 0;
    }
}

__global__ void k_scan3(int n) {
    for (int i = blockIdx.x * blockDim.x + threadIdx.x; i < n; i += gridDim.x * blockDim.x) {
        int o = g_off[i + 1] + g_bsum[i >> 10];
        g_off[i + 1] = o;
    }
}

__global__ void k_cursor(int n) {
    for (int i = blockIdx.x * blockDim.x + threadIdx.x; i < n; i += gridDim.x * blockDim.x)
        g_cursor[i] = g_off[i];
}

__global__ void k_fill(const int* __restrict__ src, const int* __restrict__ dst, int e) {
    for (int i = blockIdx.x * blockDim.x + threadIdx.x; i < e; i += gridDim.x * blockDim.x) {
        int v = dst[i];
        int p = atomicAdd(&g_cursor[v], 1);
        g_csr[p] = src[i];
    }
}

// ---------------- neighbor aggregation (warp per node, CSR gather) -----------
__global__ void k_agg(int n) {
    int warp = (blockIdx.x * blockDim.x + threadIdx.x) >> 5;
    int lane = threadIdx.x & 31;
    if (warp >= n) return;
    int beg = g_off[warp], end = g_off[warp + 1];
    float4 a0 = make_float4(0, 0, 0, 0), a1 = make_float4(0, 0, 0, 0);
    int e = beg;
    for (; e + 1 < end; e += 2) {
        int s0 = g_csr[e], s1 = g_csr[e + 1];
        const float4* p0 = (const float4*)(g_H + (size_t)s0 * 512) + lane * 2;
        const float4* p1 = (const float4*)(g_H + (size_t)s1 * 512) + lane * 2;
        float4 x0 = p0[0], x1 = p0[1];
        float4 y0 = p1[0], y1 = p1[1];
        a0 = f4add(a0, x0); a1 = f4add(a1, x1);
        a0 = f4add(a0, y0); a1 = f4add(a1, y1);
    }
    if (e < end) {
        int s0 = g_csr[e];
        const float4* p0 = (const float4*)(g_H + (size_t)s0 * 512) + lane * 2;
        a0 = f4add(a0, p0[0]); a1 = f4add(a1, p0[1]);
    }
    int deg = end - beg;
    float inv = 1.f / (float)(deg > 0 ? deg : 1);
    a0.x *= inv; a0.y *= inv; a0.z *= inv; a0.w *= inv;
    a1.x *= inv; a1.y *= inv; a1.z *= inv; a1.w *= inv;
    float4* o = (float4*)(g_H + (size_t)warp * 512 + 256) + lane * 2;
    o[0] = a0; o[1] = a1;
}

// ---------------- row L2-normalize (warp per row, width 256) -----------------
__global__ void k_norm(const float* __restrict__ src, float* __restrict__ dst, int n) {
    int warp = (blockIdx.x * blockDim.x + threadIdx.x) >> 5;
    int lane = threadIdx.x & 31;
    if (warp >= n) return;
    const float4* p = (const float4*)(src + (size_t)warp * 256) + lane * 2;
    float4 a = p[0], b = p[1];
    float s = a.x * a.x + a.y * a.y + a.z * a.z + a.w * a.w
            + b.x * b.x + b.y * b.y + b.z * b.z + b.w * b.w;
    #pragma unroll
    for (int m = 16; m > 0; m >>= 1) s += __shfl_xor_sync(0xffffffffu, s, m);
    float scale = 1.f / fmaxf(sqrtf(s), 1e-6f);
    a.x *= scale; a.y *= scale; a.z *= scale; a.w *= scale;
    b.x *= scale; b.y *= scale; b.z *= scale; b.w *= scale;
    float4* o = (float4*)(dst + (size_t)warp * 256) + lane * 2;
    o[0] = a; o[1] = b;
}

// ---------------- 2-term FP16-split tensor-core GEMM --------------------------
// C = [res +] act(A @ W^T + bias)
// A split into fp16 hi+lo; W rounded to fp16.  D = Ah*Bh + Al*Bh.
// Dropped term A*(B - Bh) ~ 2^-12 relative.
// A: M x K (lda), W: N x K row-major (ldw), C: M x N (ldc)
// Block tile 128x128, 8 warps (2m x 4n) of 64x32, K-chunk 32 (m16n8k16).
// SMEM [row][kpair] uint32 layout, stride 20 -> conflict-free fragment LDS.

#define SST 20   // smem row stride in uint32 (16 + 4 pad)

__device__ __forceinline__ float4 ldguard(const float* row, int k, int K) {
    float4 v = make_float4(0.f, 0.f, 0.f, 0.f);
    if (row) {
        if (k + 4 <= K) {
            v = *(const float4*)(row + k);
        } else {
            if (k + 0 < K) v.x = row[k + 0];
            if (k + 1 < K) v.y = row[k + 1];
            if (k + 2 < K) v.z = row[k + 2];
            if (k + 3 < K) v.w = row[k + 3];
        }
    }
    return v;
}

template <int ACT, bool RES, bool GATHER>
__global__ __launch_bounds__(256)
void k_gemm_tc(const float* __restrict__ A, int lda,
               const float* __restrict__ W, int ldw,
               const float* __restrict__ bias,
               float* __restrict__ C, int ldc,
               const int* __restrict__ rowidx,
               int M, int N, int K) {
    __shared__ unsigned int Ah[128 * SST], Al[128 * SST];
    __shared__ unsigned int Bh[128 * SST];

    const int t = threadIdx.x;
    const int wid = t >> 5, lane = t & 31;
    const int wm = (wid & 1) * 64;        // warp m offset in block
    const int wn = (wid >> 1) * 32;       // warp n offset in block
    const int bm = blockIdx.y * 128;
    const int bn = blockIdx.x * 128;

    // loader coords: each thread handles one row, 16 consecutive K floats
    const int lr = t >> 1;                 // 0..127 row in tile
    const int lk = (t & 1) * 16;           // 0 or 16 float offset in chunk

    const float* Arow = nullptr;
    if (bm + lr < M) {
        int r = GATHER ? rowidx[bm + lr] : (bm + lr);
        Arow = A + (size_t)r * lda;
    }
    const float* Brow = (bn + lr < N) ? (W + (size_t)(bn + lr) * ldw) : nullptr;

    float acc[4][4][4];
    #pragma unroll
    for (int i = 0; i < 4; i++)
        #pragma unroll
        for (int j = 0; j < 4; j++)
            #pragma unroll
            for (int r = 0; r < 4; r++) acc[i][j][r] = 0.f;

    const int nch = (K + 31) >> 5;

    // prefetch chunk 0 (4 float4 of A, 4 of B per thread)
    float4 va[4], vb[4];
    #pragma unroll
    for (int q = 0; q < 4; q++) {
        va[q] = ldguard(Arow, lk + q * 4, K);
        vb[q] = ldguard(Brow, lk + q * 4, K);
    }

    for (int c = 0; c < nch; c++) {
        // split + pack + store
        {
            unsigned int ph[8], pl[8];
            #pragma unroll
            for (int q = 0; q < 4; q++) {
                split2(va[q].x, va[q].y, ph[q * 2 + 0], pl[q * 2 + 0]);
                split2(va[q].z, va[q].w, ph[q * 2 + 1], pl[q * 2 + 1]);
            }
            int base = lr * SST + lk / 2;
            *(uint4*)(Ah + base)     = make_uint4(ph[0], ph[1], ph[2], ph[3]);
            *(uint4*)(Ah + base + 4) = make_uint4(ph[4], ph[5], ph[6], ph[7]);
            *(uint4*)(Al + base)     = make_uint4(pl[0], pl[1], pl[2], pl[3]);
            *(uint4*)(Al + base + 4) = make_uint4(pl[4], pl[5], pl[6], pl[7]);
            #pragma unroll
            for (int q = 0; q < 4; q++) {
                ph[q * 2 + 0] = pack2(vb[q].x, vb[q].y);
                ph[q * 2 + 1] = pack2(vb[q].z, vb[q].w);
            }
            *(uint4*)(Bh + base)     = make_uint4(ph[0], ph[1], ph[2], ph[3]);
            *(uint4*)(Bh + base + 4) = make_uint4(ph[4], ph[5], ph[6], ph[7]);
        }
        __syncthreads();

        if (c + 1 < nch) {
            int kn = (c + 1) * 32 + lk;
            #pragma unroll
            for (int q = 0; q < 4; q++) {
                va[q] = ldguard(Arow, kn + q * 4, K);
                vb[q] = ldguard(Brow, kn + q * 4, K);
            }
        }

        #pragma unroll
        for (int ks = 0; ks < 2; ks++) {        // two k16 sub-steps per chunk
            const int kc = ks * 8 + (lane & 3); // uint32 col index
            unsigned int ah[4][4], al[4][4];
            #pragma unroll
            for (int i = 0; i < 4; i++) {
                int m = wm + i * 16 + (lane >> 2);
                ah[i][0] = Ah[m * SST + kc];
                ah[i][1] = Ah[(m + 8) * SST + kc];
                ah[i][2] = Ah[m * SST + kc + 4];
                ah[i][3] = Ah[(m + 8) * SST + kc + 4];
                al[i][0] = Al[m * SST + kc];
                al[i][1] = Al[(m + 8) * SST + kc];
                al[i][2] = Al[m * SST + kc + 4];
                al[i][3] = Al[(m + 8) * SST + kc + 4];
            }
            unsigned int bh[4][2];
            #pragma unroll
            for (int j = 0; j < 4; j++) {
                int n = wn + j * 8 + (lane >> 2);
                bh[j][0] = Bh[n * SST + kc];
                bh[j][1] = Bh[n * SST + kc + 4];
            }
            #pragma unroll
            for (int i = 0; i < 4; i++)
                #pragma unroll
                for (int j = 0; j < 4; j++) {
                    mma16(acc[i][j], ah[i], bh[j]);   // hi*hi
                    mma16(acc[i][j], al[i], bh[j]);   // lo*hi
                }
        }
        __syncthreads();
    }

    // epilogue: c0=(g,2t) c1=(g,2t+1) c2=(g+8,2t) c3=(g+8,2t+1)
    #pragma unroll
    for (int i = 0; i < 4; i++) {
        #pragma unroll
        for (int half = 0; half < 2; half++) {
            int gm = bm + wm + i * 16 + (lane >> 2) + half * 8;
            if (gm >= M) continue;
            #pragma unroll
            for (int j = 0; j < 4; j++) {
                int gn = bn + wn + j * 8 + (lane & 3) * 2;
                if (gn >= N) continue;  // N is even, so gn+1 < N too
                float v0 = acc[i][j][half * 2 + 0] + bias[gn];
                float v1 = acc[i][j][half * 2 + 1] + bias[gn + 1];
                if (ACT == 1) { v0 = lrelu(v0); v1 = lrelu(v1); }
                size_t idx = (size_t)gm * ldc + gn;
                if (RES) { v0 += C[idx]; v1 += C[idx + 1]; }
                *(float2*)(C + idx) = make_float2(v0, v1);
            }
        }
    }
}

// ---------------- launch ------------------------------------------------------
static inline int cdiv(int a, int b) { return (a + b - 1) / b; }

extern "C" void kernel_launch(void* const* d_in, const int* in_sizes, int n_in,
                              void* d_out, int out_size) {
    const int*   node_ids = (const int*)  d_in[0];
    const float* content  = (const float*)d_in[1];
    const int*   src      = (const int*)  d_in[2];
    const int*   dst      = (const int*)  d_in[3];
    const float* emb      = (const float*)d_in[4];
    const float* W_exp    = (const float*)d_in[5];
    const float* b_exp    = (const float*)d_in[6];
    const float* W_p1     = (const float*)d_in[7];
    const float* b_p1     = (const float*)d_in[8];
    const float* W_p2     = (const float*)d_in[9];
    const float* b_p2     = (const float*)d_in[10];
    const float* W_conv   = (const float*)d_in[11];
    const float* b_conv   = (const float*)d_in[12];
    const float* Wo1      = (const float*)d_in[13];
    const float* bo1      = (const float*)d_in[14];
    const float* Wo2      = (const float*)d_in[15];
    const float* bo2      = (const float*)d_in[16];
    float* out = (float*)d_out;

    const int N = in_sizes[0];   // 50000
    const int E = in_sizes[2];   // 1000000

    float* H  = nullptr; cudaGetSymbolAddress((void**)&H,  g_H);
    float* T  = nullptr; cudaGetSymbolAddress((void**)&T,  g_T);
    float* T2 = nullptr; cudaGetSymbolAddress((void**)&T2, g_T2);
    float* T3 = nullptr; cudaGetSymbolAddress((void**)&T3, g_T3);
    int* degp = nullptr; cudaGetSymbolAddress((void**)&degp, g_deg);

    // ---- CSR build ----
    k_zero_int<<<cdiv(N, 256), 256>>>(degp, N);
    k_hist<<<cdiv(E, 256), 256>>>(dst, E);
    int nb = cdiv(N, 1024);
    k_scan1<<<nb, 1024>>>(N);
    k_scan2<<<1, 32>>>(nb);
    k_scan3<<<cdiv(N, 256), 256>>>(N);
    k_cursor<<<cdiv(N, 256), 256>>>(N);
    k_fill<<<cdiv(E, 256), 256>>>(src, dst, E);

    const int MB = cdiv(N, 128);

    // ---- initial representation ----
    {   // h = lrelu(emb[node_ids] @ W_exp^T + b_exp)  -> H[:, :256]
        dim3 g(cdiv(FF, 128), MB);
        k_gemm_tc<1, false, true><<<g, 256>>>(emb, ED, W_exp, ED, b_exp, H, 512,
                                              node_ids, N, FF, ED);
    }
    {   // T = lrelu(content @ W_p1^T + b_p1)
        dim3 g(cdiv(NC, 128), MB);
        k_gemm_tc<1, false, false><<<g, 256>>>(content, NC, W_p1, NC, b_p1, T, NC,
                                               nullptr, N, NC, NC);
    }
    {   // H[:, :256] += lrelu(T @ W_p2^T + b_p2)
        dim3 g(cdiv(FF, 128), MB);
        k_gemm_tc<1, true, false><<<g, 256>>>(T, NC, W_p2, NC, b_p2, H, 512,
                                              nullptr, N, FF, NC);
    }

    // ---- layers ----
    for (int i = 0; i < 3; i++) {
        // h_agg = segment_mean(h[src] over dst)  -> H[:, 256:512]
        k_agg<<<cdiv(N * 32, 256), 256>>>(N);

        // conv: T2 = act([h, h_agg] @ W_conv[i]^T + b_conv[i])
        dim3 g(cdiv(FF, 128), MB);
        const float* Wc = W_conv + (size_t)i * FF * 2 * FF;
        const float* bc = b_conv + (size_t)i * FF;
        if (i < 2)
            k_gemm_tc<1, false, false><<<g, 256>>>(H, 512, Wc, 2 * FF, bc, T2, FF,
                                                   nullptr, N, FF, 2 * FF);
        else
            k_gemm_tc<0, false, false><<<g, 256>>>(H, 512, Wc, 2 * FF, bc, T2, FF,
                                                   nullptr, N, FF, 2 * FF);

        // row L2 normalize
        float* ndst = (i == 2) ? out : T2;
        k_norm<<<cdiv(N * 32, 256), 256>>>(T2, ndst, N);

        if (i < 2) {
            const float* w1 = Wo1 + (size_t)i * FF * FF;
            const float* w2 = Wo2 + (size_t)i * FF * FF;
            const float* c1 = bo1 + (size_t)i * FF;
            const float* c2 = bo2 + (size_t)i * FF;
            // T3 = lrelu(T2 @ Wo1^T + bo1)
            k_gemm_tc<1, false, false><<<g, 256>>>(T2, FF, w1, FF, c1, T3, FF,
                                                   nullptr, N, FF, FF);
            // H[:, :256] = T3 @ Wo2^T + bo2
            k_gemm_tc<0, false, false><<<g, 256>>>(T3, FF, w2, FF, c2, H, 512,
                                                   nullptr, N, FF, FF);
        }
    }
}

// round 15
// speedup vs baseline: 1.1556x; 1.0004x over previous
#include <cuda_runtime.h>
#include <cuda_fp16.h>
#include <cuda_bf16.h>
#include <cstdint>
#include <stdint.h>
#include <math.h>

// Problem constants (fixed by the registry shapes)
#define NN 50000
#define NE 1000000
#define FF 256
#define NC 300
#define ED 64

// ---------------- device scratch (no runtime allocation allowed) -------------
__device__ float g_H[(size_t)NN * 512];     // [:,0:256]=h, [:,256:512]=h_agg
__device__ float g_T[(size_t)NN * NC];      // content proj temp
__device__ float g_T2[(size_t)NN * FF];     // conv output
__device__ float g_T3[(size_t)NN * FF];     // Wo1 output
__device__ int   g_deg[NN];
__device__ int   g_off[NN + 1];
__device__ int   g_cursor[NN];
__device__ int   g_csr[NE];
__device__ int   g_bsum[64];

// ---------------- small helpers ----------------------------------------------
__device__ __forceinline__ float lrelu(float x) { return x > 0.f ? x : 0.1f * x; }
__device__ __forceinline__ float4 f4add(float4 a, float4 b) {
    return make_float4(a.x + b.x, a.y + b.y, a.z + b.z, a.w + b.w);
}

// D(16x8) += A(16x16,row) * B(16x8,col) in fp16, fp32 accum
__device__ __forceinline__ void mma16(float* c, const unsigned int* a, const unsigned int* b) {
    asm volatile(
        "mma.sync.aligned.m16n8k16.row.col.f32.f16.f16.f32 "
        "{%0,%1,%2,%3},{%4,%5,%6,%7},{%8,%9},{%0,%1,%2,%3};"
        : "+f"(c[0]), "+f"(c[1]), "+f"(c[2]), "+f"(c[3])
        : "r"(a[0]), "r"(a[1]), "r"(a[2]), "r"(a[3]), "r"(b[0]), "r"(b[1]));
}

// split two floats into packed fp16x2 hi / lo parts
__device__ __forceinline__ void split2(float x0, float x1,
                                       unsigned int& hi, unsigned int& lo) {
    __half h0 = __float2half(x0);
    __half h1 = __float2half(x1);
    float r0 = x0 - __half2float(h0);
    float r1 = x1 - __half2float(h1);
    __half l0 = __float2half(r0);
    __half l1 = __float2half(r1);
    __half2 H = __halves2half2(h0, h1);
    __half2 L = __halves2half2(l0, l1);
    hi = *(unsigned int*)&H;
    lo = *(unsigned int*)&L;
}

// round two floats into packed fp16x2
__device__ __forceinline__ unsigned int pack2(float x0, float x1) {
    __half2 H = __halves2half2(__float2half(x0), __float2half(x1));
    return *(unsigned int*)&H;
}

// ---------------- CSR build ---------------------------------------------------
__global__ void k_zero_int(int* p, int n) {
    for (int i = blockIdx.x * blockDim.x + threadIdx.x; i < n; i += gridDim.x * blockDim.x)
        p[i] = 0;
}

__global__ void k_hist(const int* __restrict__ dst, int e) {
    for (int i = blockIdx.x * blockDim.x + threadIdx.x; i < e; i += gridDim.x * blockDim.x)
        atomicAdd(&g_deg[dst[i]], 1);
}

__global__ void k_scan1(int n) {
    __shared__ int s[1024];
    int t = threadIdx.x;
    int i = blockIdx.x * 1024 + t;
    int x = (i < n) ? g_deg[i] : 0;
    s[t] = x;
    __syncthreads();
    #pragma unroll
    for (int d = 1; d < 1024; d <<= 1) {
        int v = (t >= d) ? s[t - d] : 0;
        __syncthreads();
        s[t] += v;
        __syncthreads();
    }
    if (i < n) g_off[i + 1] = s[t];
    if (t == 1023) g_bsum[blockIdx.x] = s[t];
}

__global__ void k_scan2(int nb) {
    if (threadIdx.x == 0 && blockIdx.x == 0) {
        int run = 0;
        for (int b = 0; b < nb; b++) { int v = g_bsum[b]; g_bsum[b] = run; run += v; }
        g_off[0] = 0;
    }
}

__global__ void k_scan3(int n) {
    for (int i = blockIdx.x * blockDim.x + threadIdx.x; i < n; i += gridDim.x * blockDim.x) {
        int o = g_off[i + 1] + g_bsum[i >> 10];
        g_off[i + 1] = o;
    }
}

__global__ void k_cursor(int n) {
    for (int i = blockIdx.x * blockDim.x + threadIdx.x; i < n; i += gridDim.x * blockDim.x)
        g_cursor[i] = g_off[i];
}

__global__ void k_fill(const int* __restrict__ src, const int* __restrict__ dst, int e) {
    for (int i = blockIdx.x * blockDim.x + threadIdx.x; i < e; i += gridDim.x * blockDim.x) {
        int v = dst[i];
        int p = atomicAdd(&g_cursor[v], 1);
        g_csr[p] = src[i];
    }
}

// ---------------- neighbor aggregation (warp per node, CSR gather) -----------
__global__ void k_agg(int n) {
    int warp = (blockIdx.x * blockDim.x + threadIdx.x) >> 5;
    int lane = threadIdx.x & 31;
    if (warp >= n) return;
    int beg = g_off[warp], end = g_off[warp + 1];
    float4 a0 = make_float4(0, 0, 0, 0), a1 = make_float4(0, 0, 0, 0);
    int e = beg;
    for (; e + 1 < end; e += 2) {
        int s0 = g_csr[e], s1 = g_csr[e + 1];
        const float4* p0 = (const float4*)(g_H + (size_t)s0 * 512) + lane * 2;
        const float4* p1 = (const float4*)(g_H + (size_t)s1 * 512) + lane * 2;
        float4 x0 = p0[0], x1 = p0[1];
        float4 y0 = p1[0], y1 = p1[1];
        a0 = f4add(a0, x0); a1 = f4add(a1, x1);
        a0 = f4add(a0, y0); a1 = f4add(a1, y1);
    }
    if (e < end) {
        int s0 = g_csr[e];
        const float4* p0 = (const float4*)(g_H + (size_t)s0 * 512) + lane * 2;
        a0 = f4add(a0, p0[0]); a1 = f4add(a1, p0[1]);
    }
    int deg = end - beg;
    float inv = 1.f / (float)(deg > 0 ? deg : 1);
    a0.x *= inv; a0.y *= inv; a0.z *= inv; a0.w *= inv;
    a1.x *= inv; a1.y *= inv; a1.z *= inv; a1.w *= inv;
    float4* o = (float4*)(g_H + (size_t)warp * 512 + 256) + lane * 2;
    o[0] = a0; o[1] = a1;
}

// ---------------- row L2-normalize (warp per row, width 256) -----------------
__global__ void k_norm(const float* __restrict__ src, float* __restrict__ dst, int n) {
    int warp = (blockIdx.x * blockDim.x + threadIdx.x) >> 5;
    int lane = threadIdx.x & 31;
    if (warp >= n) return;
    const float4* p = (const float4*)(src + (size_t)warp * 256) + lane * 2;
    float4 a = p[0], b = p[1];
    float s = a.x * a.x + a.y * a.y + a.z * a.z + a.w * a.w
            + b.x * b.x + b.y * b.y + b.z * b.z + b.w * b.w;
    #pragma unroll
    for (int m = 16; m > 0; m >>= 1) s += __shfl_xor_sync(0xffffffffu, s, m);
    float scale = 1.f / fmaxf(sqrtf(s), 1e-6f);
    a.x *= scale; a.y *= scale; a.z *= scale; a.w *= scale;
    b.x *= scale; b.y *= scale; b.z *= scale; b.w *= scale;
    float4* o = (float4*)(dst + (size_t)warp * 256) + lane * 2;
    o[0] = a; o[1] = b;
}

// ---------------- 2-term FP16-split tensor-core GEMM --------------------------
// C = [res +] act(A @ W^T + bias)
// A split into fp16 hi+lo; W rounded to fp16.  D = Ah*Bh + Al*Bh.
// Dropped term A*(B - Bh) ~ 2^-12 relative.
// A: M x K (lda), W: N x K row-major (ldw), C: M x N (ldc)
// Block tile 128x128, 8 warps (2m x 4n) of 64x32, K-chunk 32 (m16n8k16).
// SMEM [row][kpair] uint32 layout, stride 20 -> conflict-free fragment LDS.

#define SST 20   // smem row stride in uint32 (16 + 4 pad)

__device__ __forceinline__ float4 ldguard(const float* row, int k, int K) {
    float4 v = make_float4(0.f, 0.f, 0.f, 0.f);
    if (row) {
        if (k + 4 <= K) {
            v = *(const float4*)(row + k);
        } else {
            if (k + 0 < K) v.x = row[k + 0];
            if (k + 1 < K) v.y = row[k + 1];
            if (k + 2 < K) v.z = row[k + 2];
            if (k + 3 < K) v.w = row[k + 3];
        }
    }
    return v;
}

template <int ACT, bool RES, bool GATHER>
__global__ __launch_bounds__(256)
void k_gemm_tc(const float* __restrict__ A, int lda,
               const float* __restrict__ W, int ldw,
               const float* __restrict__ bias,
               float* __restrict__ C, int ldc,
               const int* __restrict__ rowidx,
               int M, int N, int K) {
    __shared__ unsigned int Ah[128 * SST], Al[128 * SST];
    __shared__ unsigned int Bh[128 * SST];

    const int t = threadIdx.x;
    const int wid = t >> 5, lane = t & 31;
    const int wm = (wid & 1) * 64;        // warp m offset in block
    const int wn = (wid >> 1) * 32;       // warp n offset in block
    const int bm = blockIdx.y * 128;
    const int bn = blockIdx.x * 128;

    // loader coords: each thread handles one row, 16 consecutive K floats
    const int lr = t >> 1;                 // 0..127 row in tile
    const int lk = (t & 1) * 16;           // 0 or 16 float offset in chunk

    const float* Arow = nullptr;
    if (bm + lr < M) {
        int r = GATHER ? rowidx[bm + lr] : (bm + lr);
        Arow = A + (size_t)r * lda;
    }
    const float* Brow = (bn + lr < N) ? (W + (size_t)(bn + lr) * ldw) : nullptr;

    float acc[4][4][4];
    #pragma unroll
    for (int i = 0; i < 4; i++)
        #pragma unroll
        for (int j = 0; j < 4; j++)
            #pragma unroll
            for (int r = 0; r < 4; r++) acc[i][j][r] = 0.f;

    const int nch = (K + 31) >> 5;

    // prefetch chunk 0 (4 float4 of A, 4 of B per thread)
    float4 va[4], vb[4];
    #pragma unroll
    for (int q = 0; q < 4; q++) {
        va[q] = ldguard(Arow, lk + q * 4, K);
        vb[q] = ldguard(Brow, lk + q * 4, K);
    }

    for (int c = 0; c < nch; c++) {
        // split + pack + store
        {
            unsigned int ph[8], pl[8];
            #pragma unroll
            for (int q = 0; q < 4; q++) {
                split2(va[q].x, va[q].y, ph[q * 2 + 0], pl[q * 2 + 0]);
                split2(va[q].z, va[q].w, ph[q * 2 + 1], pl[q * 2 + 1]);
            }
            int base = lr * SST + lk / 2;
            *(uint4*)(Ah + base)     = make_uint4(ph[0], ph[1], ph[2], ph[3]);
            *(uint4*)(Ah + base + 4) = make_uint4(ph[4], ph[5], ph[6], ph[7]);
            *(uint4*)(Al + base)     = make_uint4(pl[0], pl[1], pl[2], pl[3]);
            *(uint4*)(Al + base + 4) = make_uint4(pl[4], pl[5], pl[6], pl[7]);
            #pragma unroll
            for (int q = 0; q < 4; q++) {
                ph[q * 2 + 0] = pack2(vb[q].x, vb[q].y);
                ph[q * 2 + 1] = pack2(vb[q].z, vb[q].w);
            }
            *(uint4*)(Bh + base)     = make_uint4(ph[0], ph[1], ph[2], ph[3]);
            *(uint4*)(Bh + base + 4) = make_uint4(ph[4], ph[5], ph[6], ph[7]);
        }
        __syncthreads();

        if (c + 1 < nch) {
            int kn = (c + 1) * 32 + lk;
            #pragma unroll
            for (int q = 0; q < 4; q++) {
                va[q] = ldguard(Arow, kn + q * 4, K);
                vb[q] = ldguard(Brow, kn + q * 4, K);
            }
        }

        #pragma unroll
        for (int ks = 0; ks < 2; ks++) {        // two k16 sub-steps per chunk
            const int kc = ks * 8 + (lane & 3); // uint32 col index
            unsigned int ah[4][4], al[4][4];
            #pragma unroll
            for (int i = 0; i < 4; i++) {
                int m = wm + i * 16 + (lane >> 2);
                ah[i][0] = Ah[m * SST + kc];
                ah[i][1] = Ah[(m + 8) * SST + kc];
                ah[i][2] = Ah[m * SST + kc + 4];
                ah[i][3] = Ah[(m + 8) * SST + kc + 4];
                al[i][0] = Al[m * SST + kc];
                al[i][1] = Al[(m + 8) * SST + kc];
                al[i][2] = Al[m * SST + kc + 4];
                al[i][3] = Al[(m + 8) * SST + kc + 4];
            }
            unsigned int bh[4][2];
            #pragma unroll
            for (int j = 0; j < 4; j++) {
                int n = wn + j * 8 + (lane >> 2);
                bh[j][0] = Bh[n * SST + kc];
                bh[j][1] = Bh[n * SST + kc + 4];
            }
            #pragma unroll
            for (int i = 0; i < 4; i++)
                #pragma unroll
                for (int j = 0; j < 4; j++) {
                    mma16(acc[i][j], ah[i], bh[j]);   // hi*hi
                    mma16(acc[i][j], al[i], bh[j]);   // lo*hi
                }
        }
        __syncthreads();
    }

    // epilogue: c0=(g,2t) c1=(g,2t+1) c2=(g+8,2t) c3=(g+8,2t+1)
    #pragma unroll
    for (int i = 0; i < 4; i++) {
        #pragma unroll
        for (int half = 0; half < 2; half++) {
            int gm = bm + wm + i * 16 + (lane >> 2) + half * 8;
            if (gm >= M) continue;
            #pragma unroll
            for (int j = 0; j < 4; j++) {
                int gn = bn + wn + j * 8 + (lane & 3) * 2;
                if (gn >= N) continue;  // N is even, so gn+1 < N too
                float v0 = acc[i][j][half * 2 + 0] + bias[gn];
                float v1 = acc[i][j][half * 2 + 1] + bias[gn + 1];
                if (ACT == 1) { v0 = lrelu(v0); v1 = lrelu(v1); }
                size_t idx = (size_t)gm * ldc + gn;
                if (RES) { v0 += C[idx]; v1 += C[idx + 1]; }
                *(float2*)(C + idx) = make_float2(v0, v1);
            }
        }
    }
}

// ---------------- launch ------------------------------------------------------
static inline int cdiv(int a, int b) { return (a + b - 1) / b; }

extern "C" void kernel_launch(void* const* d_in, const int* in_sizes, int n_in,
                              void* d_out, int out_size) {
    const int*   node_ids = (const int*)  d_in[0];
    const float* content  = (const float*)d_in[1];
    const int*   src      = (const int*)  d_in[2];
    const int*   dst      = (const int*)  d_in[3];
    const float* emb      = (const float*)d_in[4];
    const float* W_exp    = (const float*)d_in[5];
    const float* b_exp    = (const float*)d_in[6];
    const float* W_p1     = (const float*)d_in[7];
    const float* b_p1     = (const float*)d_in[8];
    const float* W_p2     = (const float*)d_in[9];
    const float* b_p2     = (const float*)d_in[10];
    const float* W_conv   = (const float*)d_in[11];
    const float* b_conv   = (const float*)d_in[12];
    const float* Wo1      = (const float*)d_in[13];
    const float* bo1      = (const float*)d_in[14];
    const float* Wo2      = (const float*)d_in[15];
    const float* bo2      = (const float*)d_in[16];
    float* out = (float*)d_out;

    const int N = in_sizes[0];   // 50000
    const int E = in_sizes[2];   // 1000000

    float* H  = nullptr; cudaGetSymbolAddress((void**)&H,  g_H);
    float* T  = nullptr; cudaGetSymbolAddress((void**)&T,  g_T);
    float* T2 = nullptr; cudaGetSymbolAddress((void**)&T2, g_T2);
    float* T3 = nullptr; cudaGetSymbolAddress((void**)&T3, g_T3);
    int* degp = nullptr; cudaGetSymbolAddress((void**)&degp, g_deg);

    // ---- CSR build ----
    k_zero_int<<<cdiv(N, 256), 256>>>(degp, N);
    k_hist<<<cdiv(E, 256), 256>>>(dst, E);
    int nb = cdiv(N, 1024);
    k_scan1<<<nb, 1024>>>(N);
    k_scan2<<<1, 32>>>(nb);
    k_scan3<<<cdiv(N, 256), 256>>>(N);
    k_cursor<<<cdiv(N, 256), 256>>>(N);
    k_fill<<<cdiv(E, 256), 256>>>(src, dst, E);

    const int MB = cdiv(N, 128);

    // ---- initial representation ----
    {   // h = lrelu(emb[node_ids] @ W_exp^T + b_exp)  -> H[:, :256]
        dim3 g(cdiv(FF, 128), MB);
        k_gemm_tc<1, false, true><<<g, 256>>>(emb, ED, W_exp, ED, b_exp, H, 512,
                                              node_ids, N, FF, ED);
    }
    {   // T = lrelu(content @ W_p1^T + b_p1)
        dim3 g(cdiv(NC, 128), MB);
        k_gemm_tc<1, false, false><<<g, 256>>>(content, NC, W_p1, NC, b_p1, T, NC,
                                               nullptr, N, NC, NC);
    }
    {   // H[:, :256] += lrelu(T @ W_p2^T + b_p2)
        dim3 g(cdiv(FF, 128), MB);
        k_gemm_tc<1, true, false><<<g, 256>>>(T, NC, W_p2, NC, b_p2, H, 512,
                                              nullptr, N, FF, NC);
    }

    // ---- layers ----
    for (int i = 0; i < 3; i++) {
        // h_agg = segment_mean(h[src] over dst)  -> H[:, 256:512]
        k_agg<<<cdiv(N * 32, 256), 256>>>(N);

        // conv: T2 = act([h, h_agg] @ W_conv[i]^T + b_conv[i])
        dim3 g(cdiv(FF, 128), MB);
        const float* Wc = W_conv + (size_t)i * FF * 2 * FF;
        const float* bc = b_conv + (size_t)i * FF;
        if (i < 2)
            k_gemm_tc<1, false, false><<<g, 256>>>(H, 512, Wc, 2 * FF, bc, T2, FF,
                                                   nullptr, N, FF, 2 * FF);
        else
            k_gemm_tc<0, false, false><<<g, 256>>>(H, 512, Wc, 2 * FF, bc, T2, FF,
                                                   nullptr, N, FF, 2 * FF);

        // row L2 normalize
        float* ndst = (i == 2) ? out : T2;
        k_norm<<<cdiv(N * 32, 256), 256>>>(T2, ndst, N);

        if (i < 2) {
            const float* w1 = Wo1 + (size_t)i * FF * FF;
            const float* w2 = Wo2 + (size_t)i * FF * FF;
            const float* c1 = bo1 + (size_t)i * FF;
            const float* c2 = bo2 + (size_t)i * FF;
            // T3 = lrelu(T2 @ Wo1^T + bo1)
            k_gemm_tc<1, false, false><<<g, 256>>>(T2, FF, w1, FF, c1, T3, FF,
                                                   nullptr, N, FF, FF);
            // H[:, :256] = T3 @ Wo2^T + bo2
            k_gemm_tc<0, false, false><<<g, 256>>>(T3, FF, w2, FF, c2, H, 512,
                                                   nullptr, N, FF, FF);
        }
    }
}